// round 15
// baseline (speedup 1.0000x reference)
#include <cuda_runtime.h>
#include <cuda_fp16.h>
#include <cstdint>

#define D_MODEL 128
#define N_SEQ   2048
#define BATCH   4
#define N_HEAD  8
#define D_K     16
#define NEG_INF -1e30f
#define LOG2E   1.4426950408889634f
#define QSCALE  (0.08838834764831843f * LOG2E)

typedef unsigned long long ull;
typedef unsigned short u16;

// ===================== helpers ==============================================
__device__ __forceinline__ float ex2f(float x) {
    float y; asm("ex2.approx.f32 %0, %1;" : "=f"(y) : "f"(x)); return y;
}
__device__ __forceinline__ uint32_t packh2(float a, float b) {
    uint32_t r; asm("cvt.rn.f16x2.f32 %0, %1, %2;" : "=r"(r) : "f"(b), "f"(a)); return r;
}
__device__ __forceinline__ void split_pair_h(float a, float b, uint32_t& hi, uint32_t& lo) {
    asm("cvt.rn.f16x2.f32 %0, %1, %2;" : "=r"(hi) : "f"(b), "f"(a));
    float ha, hb;
    asm("{.reg .b16 x,y; mov.b32 {x,y}, %2; cvt.f32.f16 %0, x; cvt.f32.f16 %1, y;}"
        : "=f"(ha), "=f"(hb) : "r"(hi));
    float ra = a - ha, rb = b - hb;
    asm("cvt.rn.f16x2.f32 %0, %1, %2;" : "=r"(lo) : "f"(rb), "f"(ra));
}
__device__ __forceinline__ void mma16816(float* c, const uint32_t* a, const uint32_t* b) {
    asm volatile("mma.sync.aligned.m16n8k16.row.col.f32.f16.f16.f32 "
        "{%0,%1,%2,%3}, {%4,%5,%6,%7}, {%8,%9}, {%0,%1,%2,%3};"
        : "+f"(c[0]), "+f"(c[1]), "+f"(c[2]), "+f"(c[3])
        : "r"(a[0]), "r"(a[1]), "r"(a[2]), "r"(a[3]), "r"(b[0]), "r"(b[1]));
}
__device__ __forceinline__ void ldmx4(uint32_t* r, uint32_t addr) {
    asm volatile("ldmatrix.sync.aligned.m8n8.x4.shared.b16 {%0,%1,%2,%3}, [%4];"
        : "=r"(r[0]), "=r"(r[1]), "=r"(r[2]), "=r"(r[3]) : "r"(addr));
}
__device__ __forceinline__ uint32_t smem_u32(const void* p) {
    uint32_t a;
    asm("{ .reg .u64 t; cvta.to.shared.u64 t, %1; cvt.u32.u64 %0, t; }" : "=r"(a) : "l"(p));
    return a;
}

// ===================== scratch ==============================================
__device__ u16 g_qh[32 * N_SEQ * 16];
__device__ u16 g_khi[32 * N_SEQ * 16], g_klo[32 * N_SEQ * 16];
__device__ u16 g_vth[32 * 16 * N_SEQ];
__device__ float g_attn[BATCH * N_SEQ * D_MODEL];

// ===================== Kernel 1: QKV projection (mma.sync, X unsplit) =======
#define XSTR 132
#define WSTR 68
#define QKV_SMEM (128 * XSTR * 4 + 2 * 128 * WSTR * 4)

__global__ __launch_bounds__(512) void qkv_proj_kernel(
    const float* __restrict__ x,
    const float* __restrict__ Wq, const float* __restrict__ bq,
    const float* __restrict__ Wk, const float* __restrict__ bk,
    const float* __restrict__ Wv, const float* __restrict__ bv)
{
    extern __shared__ __align__(16) uint32_t dsm[];
    float*    Xs  = (float*)dsm;
    uint32_t* Whi = dsm + 128 * XSTR;
    uint32_t* Wlo = Whi + 128 * WSTR;

    const int b  = blockIdx.y;
    const int n0 = blockIdx.x * 128;
    const int w  = blockIdx.z;
    const float* W    = (w == 0) ? Wq : (w == 1) ? Wk : Wv;
    const float* bias = (w == 0) ? bq : (w == 1) ? bk : bv;

    const int tid  = threadIdx.x;
    const int warp = tid >> 5, lane = tid & 31;
    const int g = lane >> 2, m4 = lane & 3;
    const int mt = warp >> 1;
    const int jh = warp & 1;
    const int mat = lane >> 3, rin = lane & 7;

#pragma unroll
    for (int it = 0; it < 8; ++it) {
        int i = tid + it * 512;
        int d = i >> 5, nn = (i & 31) * 4;
        *(float4*)&Xs[d * XSTR + nn] =
            *(const float4*)&x[((size_t)b * D_MODEL + d) * N_SEQ + n0 + nn];
    }
#pragma unroll
    for (int it = 0; it < 8; ++it) {
        int i = tid + it * 512;
        int j = i >> 5, dd = (i & 31) * 4;
        float4 wv = *(const float4*)&W[j * D_MODEL + dd];
        uint32_t h0, l0, h1, l1;
        split_pair_h(wv.x, wv.y, h0, l0);
        split_pair_h(wv.z, wv.w, h1, l1);
        Whi[j * WSTR + (dd >> 1)]     = h0;
        Whi[j * WSTR + (dd >> 1) + 1] = h1;
        Wlo[j * WSTR + (dd >> 1)]     = l0;
        Wlo[j * WSTR + (dd >> 1) + 1] = l1;
    }
    __syncthreads();

    const uint32_t wOff = (uint32_t)(((((mat >> 1) * 8 + rin) + jh * 64) * WSTR + (mat & 1) * 4) * 4);
    const uint32_t wAddrHi = smem_u32(Whi) + wOff;
    const uint32_t wAddrLo = smem_u32(Wlo) + wOff;

    float c[8][4];
#pragma unroll
    for (int jt = 0; jt < 8; ++jt)
#pragma unroll
        for (int i = 0; i < 4; ++i) c[jt][i] = 0.f;

    const int nr = mt * 16 + g;
#pragma unroll
    for (int ks = 0; ks < 8; ++ks) {
        const int d0 = ks * 16 + 2 * m4;
        uint32_t ah[4];
        ah[0] = packh2(Xs[d0 * XSTR + nr],           Xs[(d0 + 1) * XSTR + nr]);
        ah[1] = packh2(Xs[d0 * XSTR + nr + 8],       Xs[(d0 + 1) * XSTR + nr + 8]);
        ah[2] = packh2(Xs[(d0 + 8) * XSTR + nr],     Xs[(d0 + 9) * XSTR + nr]);
        ah[3] = packh2(Xs[(d0 + 8) * XSTR + nr + 8], Xs[(d0 + 9) * XSTR + nr + 8]);
#pragma unroll
        for (int jp = 0; jp < 4; ++jp) {
            uint32_t bh4[4], bl4[4];
            const uint32_t off = (uint32_t)((jp * 16 * WSTR + ks * 8) * 4);
            ldmx4(bh4, wAddrHi + off);
            ldmx4(bl4, wAddrLo + off);
#pragma unroll
            for (int q2 = 0; q2 < 2; ++q2) {
                float* cj = c[jp * 2 + q2];
                mma16816(cj, ah, bh4 + 2 * q2);
                mma16816(cj, ah, bl4 + 2 * q2);
            }
        }
    }

    const int nglob = n0 + nr;
#pragma unroll
    for (int jt = 0; jt < 8; ++jt) {
        const int j = jh * 64 + jt * 8 + 2 * m4;
        const float2 bj = *(const float2*)&bias[j];
        const int head = j >> 4, dim = j & 15;
        const int bh_ = b * N_HEAD + head;
        float v0 = c[jt][0] + bj.x, v1 = c[jt][1] + bj.y;
        float v2 = c[jt][2] + bj.x, v3 = c[jt][3] + bj.y;
        if (w == 0) {
            uint32_t p0 = packh2(v0 * QSCALE, v1 * QSCALE);
            uint32_t p1 = packh2(v2 * QSCALE, v3 * QSCALE);
            *(uint32_t*)&g_qh[((size_t)bh_ * N_SEQ + nglob) * 16 + dim]     = p0;
            *(uint32_t*)&g_qh[((size_t)bh_ * N_SEQ + nglob + 8) * 16 + dim] = p1;
        } else if (w == 1) {
            uint32_t h0, l0, h1, l1;
            split_pair_h(v0, v1, h0, l0);
            split_pair_h(v2, v3, h1, l1);
            *(uint32_t*)&g_khi[((size_t)bh_ * N_SEQ + nglob) * 16 + dim]     = h0;
            *(uint32_t*)&g_klo[((size_t)bh_ * N_SEQ + nglob) * 16 + dim]     = l0;
            *(uint32_t*)&g_khi[((size_t)bh_ * N_SEQ + nglob + 8) * 16 + dim] = h1;
            *(uint32_t*)&g_klo[((size_t)bh_ * N_SEQ + nglob + 8) * 16 + dim] = l1;
        } else {
            uint32_t p0 = packh2(v0, v1), p1 = packh2(v2, v3);
            const size_t r0 = ((size_t)bh_ * 16 + dim) * N_SEQ;
            const size_t r1 = ((size_t)bh_ * 16 + dim + 1) * N_SEQ;
            g_vth[r0 + nglob]     = (u16)(p0 & 0xffff);
            g_vth[r1 + nglob]     = (u16)(p0 >> 16);
            g_vth[r0 + nglob + 8] = (u16)(p1 & 0xffff);
            g_vth[r1 + nglob + 8] = (u16)(p1 >> 16);
        }
    }
}

// ===================== Kernel 2: mma.sync flash attention ===================
// 256 threads = 8 warps, 3 CTAs/SM. 32-key quarters (s[4][4]) for low regs;
// cross-CTA phase overlap feeds MUFU while other CTAs run MMA phases.
#define KSTRIDE 12
#define VSTRIDE 68

__global__ __launch_bounds__(256, 3) void flash_attn_mma_kernel(
    const float* __restrict__ mask)
{
    __shared__ __align__(16) uint32_t Khi_s[128 * KSTRIDE], Klo_s[128 * KSTRIDE];
    __shared__ __align__(16) uint32_t Vth_s[24 * VSTRIDE];
    __shared__ float sb[128];

    const int qt = blockIdx.x, h = blockIdx.y, b = blockIdx.z;
    const int bh = b * N_HEAD + h;
    const int tid  = threadIdx.x;
    const int warp = tid >> 5;
    const int lane = tid & 31;
    const int g  = lane >> 2;
    const int m4 = lane & 3;
    const int mat = lane >> 3, rin = lane & 7;

    // --- Q fragments ---
    uint32_t aQ[4];
    {
        const uint32_t* qh = (const uint32_t*)g_qh + (size_t)bh * N_SEQ * 8;
        const int r0 = qt * 128 + warp * 16 + g, r1 = r0 + 8;
        aQ[0] = qh[r0 * 8 + m4];     aQ[1] = qh[r1 * 8 + m4];
        aQ[2] = qh[r0 * 8 + 4 + m4]; aQ[3] = qh[r1 * 8 + 4 + m4];
    }

    const uint32_t koff = (uint32_t)((((mat >> 1) * 8 + rin) * KSTRIDE + (mat & 1) * 4) * 4);
    const uint32_t kAddrHi = smem_u32(Khi_s) + koff;
    const uint32_t kAddrLo = smem_u32(Klo_s) + koff;
    const uint32_t voff = (uint32_t)(rin * VSTRIDE * 4 + mat * 16);
    const uint32_t vAddr = smem_u32(Vth_s) + voff;

    // ones row (dim 16) + zero rows 17-23, written once
    for (int i = tid; i < 8 * VSTRIDE; i += 256) {
        int r = i / VSTRIDE;
        Vth_s[(16 + r) * VSTRIDE + (i % VSTRIDE)] = (r == 0) ? 0x3C003C00u : 0u;
    }

    // o[0..1] = output dims, o[2] col16 = l
    float o[3][4];
#pragma unroll
    for (int n = 0; n < 3; ++n)
#pragma unroll
        for (int i = 0; i < 4; ++i) o[n][i] = 0.f;
    float m_run0 = -1e30f, m_run1 = -1e30f;

#pragma unroll 1
    for (int t = 0; t < 16; ++t) {
        // --- stage K (tid<128) / Vt (tid>=128) ---
        int pred = 0;
        if (tid < 128) {
            const size_t rb = ((size_t)bh * N_SEQ + t * 128 + tid) * 16;
            const uint4* kh = (const uint4*)&g_khi[rb];
            const uint4* kl = (const uint4*)&g_klo[rb];
            uint4 h0 = kh[0], h1 = kh[1], l0 = kl[0], l1 = kl[1];
            *(uint4*)&Khi_s[tid * KSTRIDE]     = h0;
            *(uint4*)&Khi_s[tid * KSTRIDE + 4] = h1;
            *(uint4*)&Klo_s[tid * KSTRIDE]     = l0;
            *(uint4*)&Klo_s[tid * KSTRIDE + 4] = l1;
            float mv = mask[(size_t)b * N_SEQ + t * 128 + tid];
            float bias = (1.f - mv) * (NEG_INF * LOG2E);
            sb[tid] = bias;
            pred = (bias != 0.f);
        } else {
            const int t2 = tid - 128;
            const int row = t2 >> 3, seg = t2 & 7;
            const size_t sbase = ((size_t)bh * 16 + row) * N_SEQ + t * 128 + seg * 16;
            const uint4* vh = (const uint4*)&g_vth[sbase];
            uint4 h0 = vh[0], h1 = vh[1];
            *(uint4*)&Vth_s[row * VSTRIDE + seg * 8]     = h0;
            *(uint4*)&Vth_s[row * VSTRIDE + seg * 8 + 4] = h1;
        }
        const int any_mask = __syncthreads_or(pred);

        // --- four 32-key quarters ---
#pragma unroll
        for (int qq = 0; qq < 4; ++qq) {
            // ---- S = Q·(Khi+Klo) for 32 keys ----
            uint32_t bh4a[4], bl4a[4], bh4b[4], bl4b[4];
            const uint32_t ka = (uint32_t)(qq * 32 * KSTRIDE * 4);
            ldmx4(bh4a, kAddrHi + ka);
            ldmx4(bl4a, kAddrLo + ka);
            ldmx4(bh4b, kAddrHi + ka + 16 * KSTRIDE * 4);
            ldmx4(bl4b, kAddrLo + ka + 16 * KSTRIDE * 4);

            float s[4][4];
#pragma unroll
            for (int q2 = 0; q2 < 2; ++q2) {
                float* s0 = s[q2];
                s0[0] = s0[1] = s0[2] = s0[3] = 0.f;
                mma16816(s0, aQ, bh4a + 2 * q2);
                mma16816(s0, aQ, bl4a + 2 * q2);
                float* s1 = s[2 + q2];
                s1[0] = s1[1] = s1[2] = s1[3] = 0.f;
                mma16816(s1, aQ, bh4b + 2 * q2);
                mma16816(s1, aQ, bl4b + 2 * q2);
            }
            // note: s[0],s[1] = keys qq*32+{0..7,8..15}; s[2],s[3] = +{16..23,24..31}
            if (any_mask) {
#pragma unroll
                for (int c = 0; c < 4; ++c) {
                    const int kb = qq * 32 + ((c >> 1) * 16) + ((c & 1) * 8);
                    float2 sv = *(const float2*)&sb[kb + 2 * m4];
                    s[c][0] += sv.x; s[c][1] += sv.y;
                    s[c][2] += sv.x; s[c][3] += sv.y;
                }
            }
            // ---- row max over 32 keys ----
            float mx0 = fmaxf(s[0][0], s[0][1]), mx1 = fmaxf(s[0][2], s[0][3]);
#pragma unroll
            for (int c = 1; c < 4; ++c) {
                mx0 = fmaxf(mx0, fmaxf(s[c][0], s[c][1]));
                mx1 = fmaxf(mx1, fmaxf(s[c][2], s[c][3]));
            }
            mx0 = fmaxf(mx0, __shfl_xor_sync(0xffffffffu, mx0, 1));
            mx0 = fmaxf(mx0, __shfl_xor_sync(0xffffffffu, mx0, 2));
            mx1 = fmaxf(mx1, __shfl_xor_sync(0xffffffffu, mx1, 1));
            mx1 = fmaxf(mx1, __shfl_xor_sync(0xffffffffu, mx1, 2));

            const float mn0 = fmaxf(m_run0, mx0);
            const float mn1 = fmaxf(m_run1, mx1);
            const float c0 = ex2f(m_run0 - mn0);
            const float c1 = ex2f(m_run1 - mn1);
            m_run0 = mn0; m_run1 = mn1;
#pragma unroll
            for (int n = 0; n < 3; ++n) {
                o[n][0] *= c0; o[n][1] *= c0;
                o[n][2] *= c1; o[n][3] *= c1;
            }
            // ---- exp ----
#pragma unroll
            for (int c = 0; c < 4; ++c) {
                s[c][0] = ex2f(s[c][0] - mn0);
                s[c][1] = ex2f(s[c][1] - mn0);
                s[c][2] = ex2f(s[c][2] - mn1);
                s[c][3] = ex2f(s[c][3] - mn1);
            }
            // ---- PV (+ ones column for l) ----
            uint32_t vh0[4], vh1[4], vh2[4];
            const uint32_t va = vAddr + (uint32_t)(qq * 64);
            ldmx4(vh0, va);
            ldmx4(vh1, va + 8 * VSTRIDE * 4);
            ldmx4(vh2, va + 16 * VSTRIDE * 4);
#pragma unroll
            for (int q2 = 0; q2 < 2; ++q2) {
                uint32_t a[4] = {
                    packh2(s[2 * q2][0],     s[2 * q2][1]),
                    packh2(s[2 * q2][2],     s[2 * q2][3]),
                    packh2(s[2 * q2 + 1][0], s[2 * q2 + 1][1]),
                    packh2(s[2 * q2 + 1][2], s[2 * q2 + 1][3])};
                mma16816(o[0], a, vh0 + 2 * q2);
                mma16816(o[1], a, vh1 + 2 * q2);
                mma16816(o[2], a, vh2 + 2 * q2);
            }
        }
        __syncthreads();
    }

    // ---- epilogue: l lives in col 16 (m4==0 lane of each quad) ----
    const float l0 = __shfl_sync(0xffffffffu, o[2][0], lane & ~3);
    const float l1 = __shfl_sync(0xffffffffu, o[2][2], lane & ~3);
    const float i0 = 1.f / l0, i1 = 1.f / l1;
    const int r0 = qt * 128 + warp * 16 + g;
#pragma unroll
    for (int n = 0; n < 2; ++n) {
        const int dim = h * D_K + 8 * n + 2 * m4;
        float2 lo = {o[n][0] * i0, o[n][1] * i0};
        float2 hi = {o[n][2] * i1, o[n][3] * i1};
        *(float2*)&g_attn[((size_t)b * N_SEQ + r0) * D_MODEL + dim]     = lo;
        *(float2*)&g_attn[((size_t)b * N_SEQ + r0 + 8) * D_MODEL + dim] = hi;
    }
}

// ===================== Kernel 3: FC projection (mma.sync) ===================
#define ASTR 68
#define FC_SMEM (2 * 64 * ASTR * 4 + 2 * 128 * WSTR * 4)

__global__ __launch_bounds__(256) void fc_proj_kernel(
    const float* __restrict__ Wfc, const float* __restrict__ bfc,
    float* __restrict__ out)
{
    extern __shared__ __align__(16) uint32_t dsm[];
    uint32_t* Ahi = dsm;
    uint32_t* Alo = Ahi + 64 * ASTR;
    uint32_t* Whi = Alo + 64 * ASTR;
    uint32_t* Wlo = Whi + 128 * WSTR;

    const int b  = blockIdx.y;
    const int n0 = blockIdx.x * 64;
    const int tid  = threadIdx.x;
    const int warp = tid >> 5, lane = tid & 31;
    const int g = lane >> 2, m4 = lane & 3;
    const int mt = warp >> 1;
    const int jh = warp & 1;
    const int mat = lane >> 3, rin = lane & 7;

#pragma unroll
    for (int it = 0; it < 8; ++it) {
        int i = tid + it * 256;
        int n = i >> 5, dd = (i & 31) * 4;
        float4 av = *(const float4*)&g_attn[((size_t)b * N_SEQ + n0 + n) * D_MODEL + dd];
        uint32_t h0, l0, h1, l1;
        split_pair_h(av.x, av.y, h0, l0);
        split_pair_h(av.z, av.w, h1, l1);
        Ahi[n * ASTR + (dd >> 1)]     = h0;
        Ahi[n * ASTR + (dd >> 1) + 1] = h1;
        Alo[n * ASTR + (dd >> 1)]     = l0;
        Alo[n * ASTR + (dd >> 1) + 1] = l1;
    }
#pragma unroll
    for (int it = 0; it < 16; ++it) {
        int i = tid + it * 256;
        int j = i >> 5, dd = (i & 31) * 4;
        float4 wv = *(const float4*)&Wfc[j * D_MODEL + dd];
        uint32_t h0, l0, h1, l1;
        split_pair_h(wv.x, wv.y, h0, l0);
        split_pair_h(wv.z, wv.w, h1, l1);
        Whi[j * WSTR + (dd >> 1)]     = h0;
        Whi[j * WSTR + (dd >> 1) + 1] = h1;
        Wlo[j * WSTR + (dd >> 1)]     = l0;
        Wlo[j * WSTR + (dd >> 1) + 1] = l1;
    }
    __syncthreads();

    const uint32_t aOff = (uint32_t)(((((mat >> 1) * 8 + rin) + mt * 16) * ASTR + (mat & 1) * 4) * 4);
    const uint32_t aAddrHi = smem_u32(Ahi) + aOff;
    const uint32_t aAddrLo = smem_u32(Alo) + aOff;
    const uint32_t wOff = (uint32_t)(((((mat >> 1) * 8 + rin) + jh * 64) * WSTR + (mat & 1) * 4) * 4);
    const uint32_t wAddrHi = smem_u32(Whi) + wOff;
    const uint32_t wAddrLo = smem_u32(Wlo) + wOff;

    float c[8][4];
#pragma unroll
    for (int jt = 0; jt < 8; ++jt)
#pragma unroll
        for (int i = 0; i < 4; ++i) c[jt][i] = 0.f;

#pragma unroll
    for (int ks = 0; ks < 8; ++ks) {
        uint32_t mh[4], ml[4];
        ldmx4(mh, aAddrHi + (uint32_t)(ks * 32));
        ldmx4(ml, aAddrLo + (uint32_t)(ks * 32));
        uint32_t ah[4] = {mh[0], mh[2], mh[1], mh[3]};
        uint32_t al[4] = {ml[0], ml[2], ml[1], ml[3]};
#pragma unroll
        for (int jp = 0; jp < 4; ++jp) {
            uint32_t bh4[4], bl4[4];
            const uint32_t off = (uint32_t)((jp * 16 * WSTR + ks * 8) * 4);
            ldmx4(bh4, wAddrHi + off);
            ldmx4(bl4, wAddrLo + off);
#pragma unroll
            for (int q2 = 0; q2 < 2; ++q2) {
                float* cj = c[jp * 2 + q2];
                mma16816(cj, ah, bh4 + 2 * q2);
                mma16816(cj, ah, bl4 + 2 * q2);
                mma16816(cj, al, bh4 + 2 * q2);
            }
        }
    }

    const int nglob = n0 + mt * 16 + g;
#pragma unroll
    for (int jt = 0; jt < 8; ++jt) {
        const int j = jh * 64 + jt * 8 + 2 * m4;
        const float2 bj = *(const float2*)&bfc[j];
        float* o0 = &out[((size_t)b * D_MODEL + j) * N_SEQ];
        float* o1 = &out[((size_t)b * D_MODEL + j + 1) * N_SEQ];
        o0[nglob]     = c[jt][0] + bj.x;
        o1[nglob]     = c[jt][1] + bj.y;
        o0[nglob + 8] = c[jt][2] + bj.x;
        o1[nglob + 8] = c[jt][3] + bj.y;
    }
}

// ===========================================================================
extern "C" void kernel_launch(void* const* d_in, const int* in_sizes, int n_in,
                              void* d_out, int out_size)
{
    const float* x    = (const float*)d_in[0];
    const float* mask = (const float*)d_in[1];
    const float* Wq   = (const float*)d_in[2];
    const float* bq   = (const float*)d_in[3];
    const float* Wk   = (const float*)d_in[4];
    const float* bk   = (const float*)d_in[5];
    const float* Wv   = (const float*)d_in[6];
    const float* bv   = (const float*)d_in[7];
    const float* Wfc  = (const float*)d_in[8];
    const float* bfc  = (const float*)d_in[9];
    float* out = (float*)d_out;

    cudaFuncSetAttribute(qkv_proj_kernel, cudaFuncAttributeMaxDynamicSharedMemorySize, QKV_SMEM);
    cudaFuncSetAttribute(fc_proj_kernel,  cudaFuncAttributeMaxDynamicSharedMemorySize, FC_SMEM);

    qkv_proj_kernel<<<dim3(N_SEQ / 128, BATCH, 3), 512, QKV_SMEM>>>(x, Wq, bq, Wk, bk, Wv, bv);
    flash_attn_mma_kernel<<<dim3(N_SEQ / 128, N_HEAD, BATCH), 256>>>(mask);
    fc_proj_kernel<<<dim3(N_SEQ / 64, BATCH), 256, FC_SMEM>>>(Wfc, bfc, out);
}

// round 16
// speedup vs baseline: 1.1336x; 1.1336x over previous
#include <cuda_runtime.h>
#include <cuda_fp16.h>
#include <cstdint>

#define D_MODEL 128
#define N_SEQ   2048
#define BATCH   4
#define N_HEAD  8
#define D_K     16
#define NEG_INF -1e30f
#define LOG2E   1.4426950408889634f
#define QSCALE  (0.08838834764831843f * LOG2E)

typedef unsigned long long ull;
typedef unsigned short u16;

// ===================== helpers ==============================================
__device__ __forceinline__ float ex2f(float x) {
    float y; asm("ex2.approx.f32 %0, %1;" : "=f"(y) : "f"(x)); return y;
}
// packed fp16x2 exp2 — one MUFU op for two probabilities
__device__ __forceinline__ uint32_t ex2h2(uint32_t x) {
    uint32_t y; asm("ex2.approx.f16x2 %0, %1;" : "=r"(y) : "r"(x)); return y;
}
__device__ __forceinline__ uint32_t packh2(float a, float b) {
    uint32_t r; asm("cvt.rn.f16x2.f32 %0, %1, %2;" : "=r"(r) : "f"(b), "f"(a)); return r;
}
__device__ __forceinline__ void split_pair_h(float a, float b, uint32_t& hi, uint32_t& lo) {
    asm("cvt.rn.f16x2.f32 %0, %1, %2;" : "=r"(hi) : "f"(b), "f"(a));
    float ha, hb;
    asm("{.reg .b16 x,y; mov.b32 {x,y}, %2; cvt.f32.f16 %0, x; cvt.f32.f16 %1, y;}"
        : "=f"(ha), "=f"(hb) : "r"(hi));
    float ra = a - ha, rb = b - hb;
    asm("cvt.rn.f16x2.f32 %0, %1, %2;" : "=r"(lo) : "f"(rb), "f"(ra));
}
__device__ __forceinline__ void mma16816(float* c, const uint32_t* a, const uint32_t* b) {
    asm volatile("mma.sync.aligned.m16n8k16.row.col.f32.f16.f16.f32 "
        "{%0,%1,%2,%3}, {%4,%5,%6,%7}, {%8,%9}, {%0,%1,%2,%3};"
        : "+f"(c[0]), "+f"(c[1]), "+f"(c[2]), "+f"(c[3])
        : "r"(a[0]), "r"(a[1]), "r"(a[2]), "r"(a[3]), "r"(b[0]), "r"(b[1]));
}
__device__ __forceinline__ void ldmx4(uint32_t* r, uint32_t addr) {
    asm volatile("ldmatrix.sync.aligned.m8n8.x4.shared.b16 {%0,%1,%2,%3}, [%4];"
        : "=r"(r[0]), "=r"(r[1]), "=r"(r[2]), "=r"(r[3]) : "r"(addr));
}
__device__ __forceinline__ uint32_t smem_u32(const void* p) {
    uint32_t a;
    asm("{ .reg .u64 t; cvta.to.shared.u64 t, %1; cvt.u32.u64 %0, t; }" : "=r"(a) : "l"(p));
    return a;
}

// ===================== scratch ==============================================
__device__ u16 g_qh[32 * N_SEQ * 16];
__device__ u16 g_khi[32 * N_SEQ * 16], g_klo[32 * N_SEQ * 16];
__device__ u16 g_vth[32 * 16 * N_SEQ];
__device__ float g_attn[BATCH * N_SEQ * D_MODEL];

// ===================== Kernel 1: QKV projection (mma.sync, X unsplit) =======
#define XSTR 132
#define WSTR 68
#define QKV_SMEM (128 * XSTR * 4 + 2 * 128 * WSTR * 4)

__global__ __launch_bounds__(512) void qkv_proj_kernel(
    const float* __restrict__ x,
    const float* __restrict__ Wq, const float* __restrict__ bq,
    const float* __restrict__ Wk, const float* __restrict__ bk,
    const float* __restrict__ Wv, const float* __restrict__ bv)
{
    extern __shared__ __align__(16) uint32_t dsm[];
    float*    Xs  = (float*)dsm;
    uint32_t* Whi = dsm + 128 * XSTR;
    uint32_t* Wlo = Whi + 128 * WSTR;

    const int b  = blockIdx.y;
    const int n0 = blockIdx.x * 128;
    const int w  = blockIdx.z;
    const float* W    = (w == 0) ? Wq : (w == 1) ? Wk : Wv;
    const float* bias = (w == 0) ? bq : (w == 1) ? bk : bv;

    const int tid  = threadIdx.x;
    const int warp = tid >> 5, lane = tid & 31;
    const int g = lane >> 2, m4 = lane & 3;
    const int mt = warp >> 1;
    const int jh = warp & 1;
    const int mat = lane >> 3, rin = lane & 7;

#pragma unroll
    for (int it = 0; it < 8; ++it) {
        int i = tid + it * 512;
        int d = i >> 5, nn = (i & 31) * 4;
        *(float4*)&Xs[d * XSTR + nn] =
            *(const float4*)&x[((size_t)b * D_MODEL + d) * N_SEQ + n0 + nn];
    }
#pragma unroll
    for (int it = 0; it < 8; ++it) {
        int i = tid + it * 512;
        int j = i >> 5, dd = (i & 31) * 4;
        float4 wv = *(const float4*)&W[j * D_MODEL + dd];
        uint32_t h0, l0, h1, l1;
        split_pair_h(wv.x, wv.y, h0, l0);
        split_pair_h(wv.z, wv.w, h1, l1);
        Whi[j * WSTR + (dd >> 1)]     = h0;
        Whi[j * WSTR + (dd >> 1) + 1] = h1;
        Wlo[j * WSTR + (dd >> 1)]     = l0;
        Wlo[j * WSTR + (dd >> 1) + 1] = l1;
    }
    __syncthreads();

    const uint32_t wOff = (uint32_t)(((((mat >> 1) * 8 + rin) + jh * 64) * WSTR + (mat & 1) * 4) * 4);
    const uint32_t wAddrHi = smem_u32(Whi) + wOff;
    const uint32_t wAddrLo = smem_u32(Wlo) + wOff;

    float c[8][4];
#pragma unroll
    for (int jt = 0; jt < 8; ++jt)
#pragma unroll
        for (int i = 0; i < 4; ++i) c[jt][i] = 0.f;

    const int nr = mt * 16 + g;
#pragma unroll
    for (int ks = 0; ks < 8; ++ks) {
        const int d0 = ks * 16 + 2 * m4;
        uint32_t ah[4];
        ah[0] = packh2(Xs[d0 * XSTR + nr],           Xs[(d0 + 1) * XSTR + nr]);
        ah[1] = packh2(Xs[d0 * XSTR + nr + 8],       Xs[(d0 + 1) * XSTR + nr + 8]);
        ah[2] = packh2(Xs[(d0 + 8) * XSTR + nr],     Xs[(d0 + 9) * XSTR + nr]);
        ah[3] = packh2(Xs[(d0 + 8) * XSTR + nr + 8], Xs[(d0 + 9) * XSTR + nr + 8]);
#pragma unroll
        for (int jp = 0; jp < 4; ++jp) {
            uint32_t bh4[4], bl4[4];
            const uint32_t off = (uint32_t)((jp * 16 * WSTR + ks * 8) * 4);
            ldmx4(bh4, wAddrHi + off);
            ldmx4(bl4, wAddrLo + off);
#pragma unroll
            for (int q2 = 0; q2 < 2; ++q2) {
                float* cj = c[jp * 2 + q2];
                mma16816(cj, ah, bh4 + 2 * q2);
                mma16816(cj, ah, bl4 + 2 * q2);
            }
        }
    }

    const int nglob = n0 + nr;
#pragma unroll
    for (int jt = 0; jt < 8; ++jt) {
        const int j = jh * 64 + jt * 8 + 2 * m4;
        const float2 bj = *(const float2*)&bias[j];
        const int head = j >> 4, dim = j & 15;
        const int bh_ = b * N_HEAD + head;
        float v0 = c[jt][0] + bj.x, v1 = c[jt][1] + bj.y;
        float v2 = c[jt][2] + bj.x, v3 = c[jt][3] + bj.y;
        if (w == 0) {
            uint32_t p0 = packh2(v0 * QSCALE, v1 * QSCALE);
            uint32_t p1 = packh2(v2 * QSCALE, v3 * QSCALE);
            *(uint32_t*)&g_qh[((size_t)bh_ * N_SEQ + nglob) * 16 + dim]     = p0;
            *(uint32_t*)&g_qh[((size_t)bh_ * N_SEQ + nglob + 8) * 16 + dim] = p1;
        } else if (w == 1) {
            uint32_t h0, l0, h1, l1;
            split_pair_h(v0, v1, h0, l0);
            split_pair_h(v2, v3, h1, l1);
            *(uint32_t*)&g_khi[((size_t)bh_ * N_SEQ + nglob) * 16 + dim]     = h0;
            *(uint32_t*)&g_klo[((size_t)bh_ * N_SEQ + nglob) * 16 + dim]     = l0;
            *(uint32_t*)&g_khi[((size_t)bh_ * N_SEQ + nglob + 8) * 16 + dim] = h1;
            *(uint32_t*)&g_klo[((size_t)bh_ * N_SEQ + nglob + 8) * 16 + dim] = l1;
        } else {
            uint32_t p0 = packh2(v0, v1), p1 = packh2(v2, v3);
            const size_t r0 = ((size_t)bh_ * 16 + dim) * N_SEQ;
            const size_t r1 = ((size_t)bh_ * 16 + dim + 1) * N_SEQ;
            g_vth[r0 + nglob]     = (u16)(p0 & 0xffff);
            g_vth[r1 + nglob]     = (u16)(p0 >> 16);
            g_vth[r0 + nglob + 8] = (u16)(p1 & 0xffff);
            g_vth[r1 + nglob + 8] = (u16)(p1 >> 16);
        }
    }
}

// ===================== Kernel 2: mma.sync flash attention ===================
// R12 structure (64-key halves, 256 thr, 2 CTAs/SM) + f16x2 packed exp:
// exp computed directly in fp16x2 -> result IS the PV A-fragment.
#define KSTRIDE 12
#define VSTRIDE 68

__global__ __launch_bounds__(256, 2) void flash_attn_mma_kernel(
    const float* __restrict__ mask)
{
    __shared__ __align__(16) uint32_t Khi_s[128 * KSTRIDE], Klo_s[128 * KSTRIDE];
    __shared__ __align__(16) uint32_t Vth_s[24 * VSTRIDE];
    __shared__ float sb[128];

    const int qt = blockIdx.x, h = blockIdx.y, b = blockIdx.z;
    const int bh = b * N_HEAD + h;
    const int tid  = threadIdx.x;
    const int warp = tid >> 5;
    const int lane = tid & 31;
    const int g  = lane >> 2;
    const int m4 = lane & 3;
    const int mat = lane >> 3, rin = lane & 7;

    uint32_t aQ[4];
    {
        const uint32_t* qh = (const uint32_t*)g_qh + (size_t)bh * N_SEQ * 8;
        const int r0 = qt * 128 + warp * 16 + g, r1 = r0 + 8;
        aQ[0] = qh[r0 * 8 + m4];     aQ[1] = qh[r1 * 8 + m4];
        aQ[2] = qh[r0 * 8 + 4 + m4]; aQ[3] = qh[r1 * 8 + 4 + m4];
    }

    const uint32_t koff = (uint32_t)((((mat >> 1) * 8 + rin) * KSTRIDE + (mat & 1) * 4) * 4);
    const uint32_t kAddrHi = smem_u32(Khi_s) + koff;
    const uint32_t kAddrLo = smem_u32(Klo_s) + koff;
    const uint32_t voff = (uint32_t)(rin * VSTRIDE * 4 + mat * 16);
    const uint32_t vAddr = smem_u32(Vth_s) + voff;

    // ones row (dim 16) + zero rows 17-23
    for (int i = tid; i < 8 * VSTRIDE; i += 256) {
        int r = i / VSTRIDE;
        Vth_s[(16 + r) * VSTRIDE + (i % VSTRIDE)] = (r == 0) ? 0x3C003C00u : 0u;
    }

    float o[3][4];
#pragma unroll
    for (int n = 0; n < 3; ++n)
#pragma unroll
        for (int i = 0; i < 4; ++i) o[n][i] = 0.f;
    float m_run0 = -1e30f, m_run1 = -1e30f;

#pragma unroll 1
    for (int t = 0; t < 16; ++t) {
        int pred = 0;
        if (tid < 128) {
            const size_t rb = ((size_t)bh * N_SEQ + t * 128 + tid) * 16;
            const uint4* kh = (const uint4*)&g_khi[rb];
            const uint4* kl = (const uint4*)&g_klo[rb];
            uint4 h0 = kh[0], h1 = kh[1], l0 = kl[0], l1 = kl[1];
            *(uint4*)&Khi_s[tid * KSTRIDE]     = h0;
            *(uint4*)&Khi_s[tid * KSTRIDE + 4] = h1;
            *(uint4*)&Klo_s[tid * KSTRIDE]     = l0;
            *(uint4*)&Klo_s[tid * KSTRIDE + 4] = l1;
            float mv = mask[(size_t)b * N_SEQ + t * 128 + tid];
            float bias = (1.f - mv) * (NEG_INF * LOG2E);
            sb[tid] = bias;
            pred = (bias != 0.f);
        } else {
            const int t2 = tid - 128;
            const int row = t2 >> 3, seg = t2 & 7;
            const size_t sbase = ((size_t)bh * 16 + row) * N_SEQ + t * 128 + seg * 16;
            const uint4* vh = (const uint4*)&g_vth[sbase];
            uint4 h0 = vh[0], h1 = vh[1];
            *(uint4*)&Vth_s[row * VSTRIDE + seg * 8]     = h0;
            *(uint4*)&Vth_s[row * VSTRIDE + seg * 8 + 4] = h1;
        }
        const int any_mask = __syncthreads_or(pred);

#pragma unroll
        for (int hf = 0; hf < 2; ++hf) {
            float s[8][4];
            // ---- S = Q·(Khi+Klo) ----
            uint32_t kh = kAddrHi + (uint32_t)(hf * 64 * KSTRIDE * 4);
            uint32_t kl = kAddrLo + (uint32_t)(hf * 64 * KSTRIDE * 4);
#pragma unroll
            for (int i = 0; i < 4; ++i) {
                uint32_t bh4[4], bl4[4];
                ldmx4(bh4, kh); ldmx4(bl4, kl);
                kh += 16 * KSTRIDE * 4; kl += 16 * KSTRIDE * 4;
#pragma unroll
                for (int q2 = 0; q2 < 2; ++q2) {
                    float* sj = s[2 * i + q2];
                    sj[0] = sj[1] = sj[2] = sj[3] = 0.f;
                    mma16816(sj, aQ, bh4 + 2 * q2);
                    mma16816(sj, aQ, bl4 + 2 * q2);
                }
            }
            if (any_mask) {
#pragma unroll
                for (int j = 0; j < 8; ++j) {
                    float2 sv = *(const float2*)&sb[hf * 64 + 8 * j + 2 * m4];
                    s[j][0] += sv.x; s[j][1] += sv.y;
                    s[j][2] += sv.x; s[j][3] += sv.y;
                }
            }
            // ---- row max ----
            float mx0 = fmaxf(s[0][0], s[0][1]), mx1 = fmaxf(s[0][2], s[0][3]);
#pragma unroll
            for (int j = 1; j < 8; ++j) {
                mx0 = fmaxf(mx0, fmaxf(s[j][0], s[j][1]));
                mx1 = fmaxf(mx1, fmaxf(s[j][2], s[j][3]));
            }
            mx0 = fmaxf(mx0, __shfl_xor_sync(0xffffffffu, mx0, 1));
            mx0 = fmaxf(mx0, __shfl_xor_sync(0xffffffffu, mx0, 2));
            mx1 = fmaxf(mx1, __shfl_xor_sync(0xffffffffu, mx1, 1));
            mx1 = fmaxf(mx1, __shfl_xor_sync(0xffffffffu, mx1, 2));

            const float mn0 = fmaxf(m_run0, mx0);
            const float mn1 = fmaxf(m_run1, mx1);
            const float c0 = ex2f(m_run0 - mn0);
            const float c1 = ex2f(m_run1 - mn1);
            m_run0 = mn0; m_run1 = mn1;
#pragma unroll
            for (int n = 0; n < 3; ++n) {
                o[n][0] *= c0; o[n][1] *= c0;
                o[n][2] *= c1; o[n][3] *= c1;
            }
            // ---- exp directly in fp16x2: ph[j] = PV A-frag halves ----
            uint32_t ph[8][2];
#pragma unroll
            for (int j = 0; j < 8; ++j) {
                ph[j][0] = ex2h2(packh2(s[j][0] - mn0, s[j][1] - mn0));
                ph[j][1] = ex2h2(packh2(s[j][2] - mn1, s[j][3] - mn1));
            }
            // ---- PV (+ ones column for l) ----
#pragma unroll
            for (int cc = 0; cc < 2; ++cc) {
                const int cp = 2 * hf + cc;
                uint32_t vh0[4], vh1[4], vh2[4];
                const uint32_t va = vAddr + (uint32_t)(cp * 64);
                ldmx4(vh0, va);
                ldmx4(vh1, va + 8 * VSTRIDE * 4);
                ldmx4(vh2, va + 16 * VSTRIDE * 4);
#pragma unroll
                for (int q2 = 0; q2 < 2; ++q2) {
                    const int c = 2 * cc + q2;
                    uint32_t a[4] = {ph[2 * c][0], ph[2 * c][1],
                                     ph[2 * c + 1][0], ph[2 * c + 1][1]};
                    mma16816(o[0], a, vh0 + 2 * q2);
                    mma16816(o[1], a, vh1 + 2 * q2);
                    mma16816(o[2], a, vh2 + 2 * q2);
                }
            }
        }
        __syncthreads();
    }

    const float l0 = __shfl_sync(0xffffffffu, o[2][0], lane & ~3);
    const float l1 = __shfl_sync(0xffffffffu, o[2][2], lane & ~3);
    const float i0 = 1.f / l0, i1 = 1.f / l1;
    const int r0 = qt * 128 + warp * 16 + g;
#pragma unroll
    for (int n = 0; n < 2; ++n) {
        const int dim = h * D_K + 8 * n + 2 * m4;
        float2 lo = {o[n][0] * i0, o[n][1] * i0};
        float2 hi = {o[n][2] * i1, o[n][3] * i1};
        *(float2*)&g_attn[((size_t)b * N_SEQ + r0) * D_MODEL + dim]     = lo;
        *(float2*)&g_attn[((size_t)b * N_SEQ + r0 + 8) * D_MODEL + dim] = hi;
    }
}

// ===================== Kernel 3: FC projection (mma.sync) ===================
#define ASTR 68
#define FC_SMEM (2 * 64 * ASTR * 4 + 2 * 128 * WSTR * 4)

__global__ __launch_bounds__(256) void fc_proj_kernel(
    const float* __restrict__ Wfc, const float* __restrict__ bfc,
    float* __restrict__ out)
{
    extern __shared__ __align__(16) uint32_t dsm[];
    uint32_t* Ahi = dsm;
    uint32_t* Alo = Ahi + 64 * ASTR;
    uint32_t* Whi = Alo + 64 * ASTR;
    uint32_t* Wlo = Whi + 128 * WSTR;

    const int b  = blockIdx.y;
    const int n0 = blockIdx.x * 64;
    const int tid  = threadIdx.x;
    const int warp = tid >> 5, lane = tid & 31;
    const int g = lane >> 2, m4 = lane & 3;
    const int mt = warp >> 1;
    const int jh = warp & 1;
    const int mat = lane >> 3, rin = lane & 7;

#pragma unroll
    for (int it = 0; it < 8; ++it) {
        int i = tid + it * 256;
        int n = i >> 5, dd = (i & 31) * 4;
        float4 av = *(const float4*)&g_attn[((size_t)b * N_SEQ + n0 + n) * D_MODEL + dd];
        uint32_t h0, l0, h1, l1;
        split_pair_h(av.x, av.y, h0, l0);
        split_pair_h(av.z, av.w, h1, l1);
        Ahi[n * ASTR + (dd >> 1)]     = h0;
        Ahi[n * ASTR + (dd >> 1) + 1] = h1;
        Alo[n * ASTR + (dd >> 1)]     = l0;
        Alo[n * ASTR + (dd >> 1) + 1] = l1;
    }
#pragma unroll
    for (int it = 0; it < 16; ++it) {
        int i = tid + it * 256;
        int j = i >> 5, dd = (i & 31) * 4;
        float4 wv = *(const float4*)&Wfc[j * D_MODEL + dd];
        uint32_t h0, l0, h1, l1;
        split_pair_h(wv.x, wv.y, h0, l0);
        split_pair_h(wv.z, wv.w, h1, l1);
        Whi[j * WSTR + (dd >> 1)]     = h0;
        Whi[j * WSTR + (dd >> 1) + 1] = h1;
        Wlo[j * WSTR + (dd >> 1)]     = l0;
        Wlo[j * WSTR + (dd >> 1) + 1] = l1;
    }
    __syncthreads();

    const uint32_t aOff = (uint32_t)(((((mat >> 1) * 8 + rin) + mt * 16) * ASTR + (mat & 1) * 4) * 4);
    const uint32_t aAddrHi = smem_u32(Ahi) + aOff;
    const uint32_t aAddrLo = smem_u32(Alo) + aOff;
    const uint32_t wOff = (uint32_t)(((((mat >> 1) * 8 + rin) + jh * 64) * WSTR + (mat & 1) * 4) * 4);
    const uint32_t wAddrHi = smem_u32(Whi) + wOff;
    const uint32_t wAddrLo = smem_u32(Wlo) + wOff;

    float c[8][4];
#pragma unroll
    for (int jt = 0; jt < 8; ++jt)
#pragma unroll
        for (int i = 0; i < 4; ++i) c[jt][i] = 0.f;

#pragma unroll
    for (int ks = 0; ks < 8; ++ks) {
        uint32_t mh[4], ml[4];
        ldmx4(mh, aAddrHi + (uint32_t)(ks * 32));
        ldmx4(ml, aAddrLo + (uint32_t)(ks * 32));
        uint32_t ah[4] = {mh[0], mh[2], mh[1], mh[3]};
        uint32_t al[4] = {ml[0], ml[2], ml[1], ml[3]};
#pragma unroll
        for (int jp = 0; jp < 4; ++jp) {
            uint32_t bh4[4], bl4[4];
            const uint32_t off = (uint32_t)((jp * 16 * WSTR + ks * 8) * 4);
            ldmx4(bh4, wAddrHi + off);
            ldmx4(bl4, wAddrLo + off);
#pragma unroll
            for (int q2 = 0; q2 < 2; ++q2) {
                float* cj = c[jp * 2 + q2];
                mma16816(cj, ah, bh4 + 2 * q2);
                mma16816(cj, ah, bl4 + 2 * q2);
                mma16816(cj, al, bh4 + 2 * q2);
            }
        }
    }

    const int nglob = n0 + mt * 16 + g;
#pragma unroll
    for (int jt = 0; jt < 8; ++jt) {
        const int j = jh * 64 + jt * 8 + 2 * m4;
        const float2 bj = *(const float2*)&bfc[j];
        float* o0 = &out[((size_t)b * D_MODEL + j) * N_SEQ];
        float* o1 = &out[((size_t)b * D_MODEL + j + 1) * N_SEQ];
        o0[nglob]     = c[jt][0] + bj.x;
        o1[nglob]     = c[jt][1] + bj.y;
        o0[nglob + 8] = c[jt][2] + bj.x;
        o1[nglob + 8] = c[jt][3] + bj.y;
    }
}

// ===========================================================================
extern "C" void kernel_launch(void* const* d_in, const int* in_sizes, int n_in,
                              void* d_out, int out_size)
{
    const float* x    = (const float*)d_in[0];
    const float* mask = (const float*)d_in[1];
    const float* Wq   = (const float*)d_in[2];
    const float* bq   = (const float*)d_in[3];
    const float* Wk   = (const float*)d_in[4];
    const float* bk   = (const float*)d_in[5];
    const float* Wv   = (const float*)d_in[6];
    const float* bv   = (const float*)d_in[7];
    const float* Wfc  = (const float*)d_in[8];
    const float* bfc  = (const float*)d_in[9];
    float* out = (float*)d_out;

    cudaFuncSetAttribute(qkv_proj_kernel, cudaFuncAttributeMaxDynamicSharedMemorySize, QKV_SMEM);
    cudaFuncSetAttribute(fc_proj_kernel,  cudaFuncAttributeMaxDynamicSharedMemorySize, FC_SMEM);

    qkv_proj_kernel<<<dim3(N_SEQ / 128, BATCH, 3), 512, QKV_SMEM>>>(x, Wq, bq, Wk, bk, Wv, bv);
    flash_attn_mma_kernel<<<dim3(N_SEQ / 128, N_HEAD, BATCH), 256>>>(mask);
    fc_proj_kernel<<<dim3(N_SEQ / 64, BATCH), 256, FC_SMEM>>>(Wfc, bfc, out);
}

// round 17
// speedup vs baseline: 1.2578x; 1.1096x over previous
#include <cuda_runtime.h>
#include <cuda_fp16.h>
#include <cstdint>

#define D_MODEL 128
#define N_SEQ   2048
#define BATCH   4
#define N_HEAD  8
#define D_K     16
#define NEG_INF -1e30f
#define LOG2E   1.4426950408889634f
#define QSCALE  (0.08838834764831843f * LOG2E)

typedef unsigned long long ull;
typedef unsigned short u16;

// ===================== helpers ==============================================
__device__ __forceinline__ float ex2f(float x) {
    float y; asm("ex2.approx.f32 %0, %1;" : "=f"(y) : "f"(x)); return y;
}
__device__ __forceinline__ uint32_t ex2h2(uint32_t x) {
    uint32_t y; asm("ex2.approx.f16x2 %0, %1;" : "=r"(y) : "r"(x)); return y;
}
__device__ __forceinline__ uint32_t packh2(float a, float b) {
    uint32_t r; asm("cvt.rn.f16x2.f32 %0, %1, %2;" : "=r"(r) : "f"(b), "f"(a)); return r;
}
__device__ __forceinline__ void split_pair_h(float a, float b, uint32_t& hi, uint32_t& lo) {
    asm("cvt.rn.f16x2.f32 %0, %1, %2;" : "=r"(hi) : "f"(b), "f"(a));
    float ha, hb;
    asm("{.reg .b16 x,y; mov.b32 {x,y}, %2; cvt.f32.f16 %0, x; cvt.f32.f16 %1, y;}"
        : "=f"(ha), "=f"(hb) : "r"(hi));
    float ra = a - ha, rb = b - hb;
    asm("cvt.rn.f16x2.f32 %0, %1, %2;" : "=r"(lo) : "f"(rb), "f"(ra));
}
__device__ __forceinline__ void mma16816(float* c, const uint32_t* a, const uint32_t* b) {
    asm volatile("mma.sync.aligned.m16n8k16.row.col.f32.f16.f16.f32 "
        "{%0,%1,%2,%3}, {%4,%5,%6,%7}, {%8,%9}, {%0,%1,%2,%3};"
        : "+f"(c[0]), "+f"(c[1]), "+f"(c[2]), "+f"(c[3])
        : "r"(a[0]), "r"(a[1]), "r"(a[2]), "r"(a[3]), "r"(b[0]), "r"(b[1]));
}
__device__ __forceinline__ void ldmx4(uint32_t* r, uint32_t addr) {
    asm volatile("ldmatrix.sync.aligned.m8n8.x4.shared.b16 {%0,%1,%2,%3}, [%4];"
        : "=r"(r[0]), "=r"(r[1]), "=r"(r[2]), "=r"(r[3]) : "r"(addr));
}
__device__ __forceinline__ uint32_t smem_u32(const void* p) {
    uint32_t a;
    asm("{ .reg .u64 t; cvta.to.shared.u64 t, %1; cvt.u32.u64 %0, t; }" : "=r"(a) : "l"(p));
    return a;
}

// ===================== scratch ==============================================
__device__ u16 g_qh[32 * N_SEQ * 16];
__device__ u16 g_khi[32 * N_SEQ * 16], g_klo[32 * N_SEQ * 16];
__device__ u16 g_vth[32 * 16 * N_SEQ];
__device__ float g_attn[BATCH * N_SEQ * D_MODEL];

// ===================== Kernel 1: QKV projection (packed-X, 2 CTA/SM) ========
#define XSTR2 136    // u32 per d-pair row (136 ≡ 8 mod 32 -> conflict-free A-frag)
#define WSTR  68
#define QKV_SMEM (64 * XSTR2 * 4 + 2 * 128 * WSTR * 4)   // 34816 + 69632 = 104448

__global__ __launch_bounds__(512, 2) void qkv_proj_kernel(
    const float* __restrict__ x,
    const float* __restrict__ Wq, const float* __restrict__ bq,
    const float* __restrict__ Wk, const float* __restrict__ bk,
    const float* __restrict__ Wv, const float* __restrict__ bv)
{
    extern __shared__ __align__(16) uint32_t dsm[];
    uint32_t* Xp  = dsm;                     // [64][XSTR2] fp16x2 (d-pair, d+1 high)
    uint32_t* Whi = dsm + 64 * XSTR2;        // [128][WSTR]
    uint32_t* Wlo = Whi + 128 * WSTR;

    const int b  = blockIdx.y;
    const int n0 = blockIdx.x * 128;
    const int w  = blockIdx.z;
    const float* W    = (w == 0) ? Wq : (w == 1) ? Wk : Wv;
    const float* bias = (w == 0) ? bq : (w == 1) ? bk : bv;

    const int tid  = threadIdx.x;
    const int warp = tid >> 5, lane = tid & 31;
    const int g = lane >> 2, m4 = lane & 3;
    const int mt = warp >> 1;
    const int jh = warp & 1;
    const int mat = lane >> 3, rin = lane & 7;

    // stage X packed fp16 [d/2][n]
#pragma unroll
    for (int it = 0; it < 4; ++it) {
        int i = tid + it * 512;               // 2048 units of 4 n-values
        int dp = i >> 5, nn = (i & 31) * 4;
        const float* r0 = &x[((size_t)b * D_MODEL + 2 * dp) * N_SEQ + n0 + nn];
        float4 a = *(const float4*)r0;
        float4 bb = *(const float4*)(r0 + N_SEQ);
        uint4 p;
        p.x = packh2(a.x, bb.x); p.y = packh2(a.y, bb.y);
        p.z = packh2(a.z, bb.z); p.w = packh2(a.w, bb.w);
        *(uint4*)&Xp[dp * XSTR2 + nn] = p;
    }
    // stage W split fp16 [j][d]
#pragma unroll
    for (int it = 0; it < 8; ++it) {
        int i = tid + it * 512;
        int j = i >> 5, dd = (i & 31) * 4;
        float4 wv = *(const float4*)&W[j * D_MODEL + dd];
        uint32_t h0, l0, h1, l1;
        split_pair_h(wv.x, wv.y, h0, l0);
        split_pair_h(wv.z, wv.w, h1, l1);
        Whi[j * WSTR + (dd >> 1)]     = h0;
        Whi[j * WSTR + (dd >> 1) + 1] = h1;
        Wlo[j * WSTR + (dd >> 1)]     = l0;
        Wlo[j * WSTR + (dd >> 1) + 1] = l1;
    }
    __syncthreads();

    const uint32_t wOff = (uint32_t)(((((mat >> 1) * 8 + rin) + jh * 64) * WSTR + (mat & 1) * 4) * 4);
    const uint32_t wAddrHi = smem_u32(Whi) + wOff;
    const uint32_t wAddrLo = smem_u32(Wlo) + wOff;

    float c[8][4];
#pragma unroll
    for (int jt = 0; jt < 8; ++jt)
#pragma unroll
        for (int i = 0; i < 4; ++i) c[jt][i] = 0.f;

    const int nr = mt * 16 + g;
#pragma unroll
    for (int ks = 0; ks < 8; ++ks) {
        const int pr = ks * 8 + m4;           // d-pair row
        uint32_t ah[4];
        ah[0] = Xp[pr * XSTR2 + nr];
        ah[1] = Xp[pr * XSTR2 + nr + 8];
        ah[2] = Xp[(pr + 4) * XSTR2 + nr];
        ah[3] = Xp[(pr + 4) * XSTR2 + nr + 8];
#pragma unroll
        for (int jp = 0; jp < 4; ++jp) {
            uint32_t bh4[4], bl4[4];
            const uint32_t off = (uint32_t)((jp * 16 * WSTR + ks * 8) * 4);
            ldmx4(bh4, wAddrHi + off);
            ldmx4(bl4, wAddrLo + off);
#pragma unroll
            for (int q2 = 0; q2 < 2; ++q2) {
                float* cj = c[jp * 2 + q2];
                mma16816(cj, ah, bh4 + 2 * q2);
                mma16816(cj, ah, bl4 + 2 * q2);
            }
        }
    }

    const int nglob = n0 + nr;
#pragma unroll
    for (int jt = 0; jt < 8; ++jt) {
        const int j = jh * 64 + jt * 8 + 2 * m4;
        const float2 bj = *(const float2*)&bias[j];
        const int head = j >> 4, dim = j & 15;
        const int bh_ = b * N_HEAD + head;
        float v0 = c[jt][0] + bj.x, v1 = c[jt][1] + bj.y;
        float v2 = c[jt][2] + bj.x, v3 = c[jt][3] + bj.y;
        if (w == 0) {
            uint32_t p0 = packh2(v0 * QSCALE, v1 * QSCALE);
            uint32_t p1 = packh2(v2 * QSCALE, v3 * QSCALE);
            *(uint32_t*)&g_qh[((size_t)bh_ * N_SEQ + nglob) * 16 + dim]     = p0;
            *(uint32_t*)&g_qh[((size_t)bh_ * N_SEQ + nglob + 8) * 16 + dim] = p1;
        } else if (w == 1) {
            uint32_t h0, l0, h1, l1;
            split_pair_h(v0, v1, h0, l0);
            split_pair_h(v2, v3, h1, l1);
            *(uint32_t*)&g_khi[((size_t)bh_ * N_SEQ + nglob) * 16 + dim]     = h0;
            *(uint32_t*)&g_klo[((size_t)bh_ * N_SEQ + nglob) * 16 + dim]     = l0;
            *(uint32_t*)&g_khi[((size_t)bh_ * N_SEQ + nglob + 8) * 16 + dim] = h1;
            *(uint32_t*)&g_klo[((size_t)bh_ * N_SEQ + nglob + 8) * 16 + dim] = l1;
        } else {
            uint32_t p0 = packh2(v0, v1), p1 = packh2(v2, v3);
            const size_t r0 = ((size_t)bh_ * 16 + dim) * N_SEQ;
            const size_t r1 = ((size_t)bh_ * 16 + dim + 1) * N_SEQ;
            g_vth[r0 + nglob]     = (u16)(p0 & 0xffff);
            g_vth[r1 + nglob]     = (u16)(p0 >> 16);
            g_vth[r0 + nglob + 8] = (u16)(p1 & 0xffff);
            g_vth[r1 + nglob + 8] = (u16)(p1 >> 16);
        }
    }
}

// ===================== Kernel 2: mma.sync flash attention ===================
// 2 q-tiles (256 q rows) per CTA share each K/V staging; f16x2 packed exp.
// Grid (8, 8, 4) = 256 CTAs @ 2/SM = 0.86 waves.
#define KSTRIDE 12
#define VSTRIDE 68

__global__ __launch_bounds__(256, 2) void flash_attn_mma_kernel(
    const float* __restrict__ mask)
{
    __shared__ __align__(16) uint32_t Khi_s[128 * KSTRIDE], Klo_s[128 * KSTRIDE];
    __shared__ __align__(16) uint32_t Vth_s[24 * VSTRIDE];
    __shared__ float sb[128];

    const int qt = blockIdx.x, h = blockIdx.y, b = blockIdx.z;
    const int bh = b * N_HEAD + h;
    const int tid  = threadIdx.x;
    const int warp = tid >> 5;
    const int lane = tid & 31;
    const int g  = lane >> 2;
    const int m4 = lane & 3;
    const int mat = lane >> 3, rin = lane & 7;

    // --- Q fragments for both q-tile sets ---
    uint32_t aQ[2][4];
    {
        const uint32_t* qh = (const uint32_t*)g_qh + (size_t)bh * N_SEQ * 8;
#pragma unroll
        for (int mt2 = 0; mt2 < 2; ++mt2) {
            const int r0 = qt * 256 + mt2 * 128 + warp * 16 + g, r1 = r0 + 8;
            aQ[mt2][0] = qh[r0 * 8 + m4];     aQ[mt2][1] = qh[r1 * 8 + m4];
            aQ[mt2][2] = qh[r0 * 8 + 4 + m4]; aQ[mt2][3] = qh[r1 * 8 + 4 + m4];
        }
    }

    const uint32_t koff = (uint32_t)((((mat >> 1) * 8 + rin) * KSTRIDE + (mat & 1) * 4) * 4);
    const uint32_t kAddrHi = smem_u32(Khi_s) + koff;
    const uint32_t kAddrLo = smem_u32(Klo_s) + koff;
    const uint32_t voff = (uint32_t)(rin * VSTRIDE * 4 + mat * 16);
    const uint32_t vAddr = smem_u32(Vth_s) + voff;

    // ones row (dim 16) + zero rows 17-23
    for (int i = tid; i < 8 * VSTRIDE; i += 256) {
        int r = i / VSTRIDE;
        Vth_s[(16 + r) * VSTRIDE + (i % VSTRIDE)] = (r == 0) ? 0x3C003C00u : 0u;
    }

    float o[2][3][4];
#pragma unroll
    for (int mt2 = 0; mt2 < 2; ++mt2)
#pragma unroll
        for (int n = 0; n < 3; ++n)
#pragma unroll
            for (int i = 0; i < 4; ++i) o[mt2][n][i] = 0.f;
    float m_run[2][2] = {{-1e30f, -1e30f}, {-1e30f, -1e30f}};

#pragma unroll 1
    for (int t = 0; t < 16; ++t) {
        int pred = 0;
        if (tid < 128) {
            const size_t rb = ((size_t)bh * N_SEQ + t * 128 + tid) * 16;
            const uint4* kh = (const uint4*)&g_khi[rb];
            const uint4* kl = (const uint4*)&g_klo[rb];
            uint4 h0 = kh[0], h1 = kh[1], l0 = kl[0], l1 = kl[1];
            *(uint4*)&Khi_s[tid * KSTRIDE]     = h0;
            *(uint4*)&Khi_s[tid * KSTRIDE + 4] = h1;
            *(uint4*)&Klo_s[tid * KSTRIDE]     = l0;
            *(uint4*)&Klo_s[tid * KSTRIDE + 4] = l1;
            float mv = mask[(size_t)b * N_SEQ + t * 128 + tid];
            float bias = (1.f - mv) * (NEG_INF * LOG2E);
            sb[tid] = bias;
            pred = (bias != 0.f);
        } else {
            const int t2 = tid - 128;
            const int row = t2 >> 3, seg = t2 & 7;
            const size_t sbase = ((size_t)bh * 16 + row) * N_SEQ + t * 128 + seg * 16;
            const uint4* vh = (const uint4*)&g_vth[sbase];
            uint4 h0 = vh[0], h1 = vh[1];
            *(uint4*)&Vth_s[row * VSTRIDE + seg * 8]     = h0;
            *(uint4*)&Vth_s[row * VSTRIDE + seg * 8 + 4] = h1;
        }
        const int any_mask = __syncthreads_or(pred);

#pragma unroll
        for (int mt2 = 0; mt2 < 2; ++mt2) {
#pragma unroll
            for (int hf = 0; hf < 2; ++hf) {
                float s[8][4];
                uint32_t kh = kAddrHi + (uint32_t)(hf * 64 * KSTRIDE * 4);
                uint32_t kl = kAddrLo + (uint32_t)(hf * 64 * KSTRIDE * 4);
#pragma unroll
                for (int i = 0; i < 4; ++i) {
                    uint32_t bh4[4], bl4[4];
                    ldmx4(bh4, kh); ldmx4(bl4, kl);
                    kh += 16 * KSTRIDE * 4; kl += 16 * KSTRIDE * 4;
#pragma unroll
                    for (int q2 = 0; q2 < 2; ++q2) {
                        float* sj = s[2 * i + q2];
                        sj[0] = sj[1] = sj[2] = sj[3] = 0.f;
                        mma16816(sj, aQ[mt2], bh4 + 2 * q2);
                        mma16816(sj, aQ[mt2], bl4 + 2 * q2);
                    }
                }
                if (any_mask) {
#pragma unroll
                    for (int j = 0; j < 8; ++j) {
                        float2 sv = *(const float2*)&sb[hf * 64 + 8 * j + 2 * m4];
                        s[j][0] += sv.x; s[j][1] += sv.y;
                        s[j][2] += sv.x; s[j][3] += sv.y;
                    }
                }
                float mx0 = fmaxf(s[0][0], s[0][1]), mx1 = fmaxf(s[0][2], s[0][3]);
#pragma unroll
                for (int j = 1; j < 8; ++j) {
                    mx0 = fmaxf(mx0, fmaxf(s[j][0], s[j][1]));
                    mx1 = fmaxf(mx1, fmaxf(s[j][2], s[j][3]));
                }
                mx0 = fmaxf(mx0, __shfl_xor_sync(0xffffffffu, mx0, 1));
                mx0 = fmaxf(mx0, __shfl_xor_sync(0xffffffffu, mx0, 2));
                mx1 = fmaxf(mx1, __shfl_xor_sync(0xffffffffu, mx1, 1));
                mx1 = fmaxf(mx1, __shfl_xor_sync(0xffffffffu, mx1, 2));

                const float mn0 = fmaxf(m_run[mt2][0], mx0);
                const float mn1 = fmaxf(m_run[mt2][1], mx1);
                const float c0 = ex2f(m_run[mt2][0] - mn0);
                const float c1 = ex2f(m_run[mt2][1] - mn1);
                m_run[mt2][0] = mn0; m_run[mt2][1] = mn1;
#pragma unroll
                for (int n = 0; n < 3; ++n) {
                    o[mt2][n][0] *= c0; o[mt2][n][1] *= c0;
                    o[mt2][n][2] *= c1; o[mt2][n][3] *= c1;
                }
                // exp directly in fp16x2 -> PV A-frags
                uint32_t ph[8][2];
#pragma unroll
                for (int j = 0; j < 8; ++j) {
                    ph[j][0] = ex2h2(packh2(s[j][0] - mn0, s[j][1] - mn0));
                    ph[j][1] = ex2h2(packh2(s[j][2] - mn1, s[j][3] - mn1));
                }
#pragma unroll
                for (int cc = 0; cc < 2; ++cc) {
                    const int cp = 2 * hf + cc;
                    uint32_t vh0[4], vh1[4], vh2[4];
                    const uint32_t va = vAddr + (uint32_t)(cp * 64);
                    ldmx4(vh0, va);
                    ldmx4(vh1, va + 8 * VSTRIDE * 4);
                    ldmx4(vh2, va + 16 * VSTRIDE * 4);
#pragma unroll
                    for (int q2 = 0; q2 < 2; ++q2) {
                        const int c = 2 * cc + q2;
                        uint32_t a[4] = {ph[2 * c][0], ph[2 * c][1],
                                         ph[2 * c + 1][0], ph[2 * c + 1][1]};
                        mma16816(o[mt2][0], a, vh0 + 2 * q2);
                        mma16816(o[mt2][1], a, vh1 + 2 * q2);
                        mma16816(o[mt2][2], a, vh2 + 2 * q2);
                    }
                }
            }
        }
        __syncthreads();
    }

    // ---- epilogue ----
#pragma unroll
    for (int mt2 = 0; mt2 < 2; ++mt2) {
        const float l0 = __shfl_sync(0xffffffffu, o[mt2][2][0], lane & ~3);
        const float l1 = __shfl_sync(0xffffffffu, o[mt2][2][2], lane & ~3);
        const float i0 = 1.f / l0, i1 = 1.f / l1;
        const int r0 = qt * 256 + mt2 * 128 + warp * 16 + g;
#pragma unroll
        for (int n = 0; n < 2; ++n) {
            const int dim = h * D_K + 8 * n + 2 * m4;
            float2 lo = {o[mt2][n][0] * i0, o[mt2][n][1] * i0};
            float2 hi = {o[mt2][n][2] * i1, o[mt2][n][3] * i1};
            *(float2*)&g_attn[((size_t)b * N_SEQ + r0) * D_MODEL + dim]     = lo;
            *(float2*)&g_attn[((size_t)b * N_SEQ + r0 + 8) * D_MODEL + dim] = hi;
        }
    }
}

// ===================== Kernel 3: FC projection (mma.sync) ===================
#define ASTR 68
#define FC_SMEM (2 * 64 * ASTR * 4 + 2 * 128 * WSTR * 4)

__global__ __launch_bounds__(256) void fc_proj_kernel(
    const float* __restrict__ Wfc, const float* __restrict__ bfc,
    float* __restrict__ out)
{
    extern __shared__ __align__(16) uint32_t dsm[];
    uint32_t* Ahi = dsm;
    uint32_t* Alo = Ahi + 64 * ASTR;
    uint32_t* Whi = Alo + 64 * ASTR;
    uint32_t* Wlo = Whi + 128 * WSTR;

    const int b  = blockIdx.y;
    const int n0 = blockIdx.x * 64;
    const int tid  = threadIdx.x;
    const int warp = tid >> 5, lane = tid & 31;
    const int g = lane >> 2, m4 = lane & 3;
    const int mt = warp >> 1;
    const int jh = warp & 1;
    const int mat = lane >> 3, rin = lane & 7;

#pragma unroll
    for (int it = 0; it < 8; ++it) {
        int i = tid + it * 256;
        int n = i >> 5, dd = (i & 31) * 4;
        float4 av = *(const float4*)&g_attn[((size_t)b * N_SEQ + n0 + n) * D_MODEL + dd];
        uint32_t h0, l0, h1, l1;
        split_pair_h(av.x, av.y, h0, l0);
        split_pair_h(av.z, av.w, h1, l1);
        Ahi[n * ASTR + (dd >> 1)]     = h0;
        Ahi[n * ASTR + (dd >> 1) + 1] = h1;
        Alo[n * ASTR + (dd >> 1)]     = l0;
        Alo[n * ASTR + (dd >> 1) + 1] = l1;
    }
#pragma unroll
    for (int it = 0; it < 16; ++it) {
        int i = tid + it * 256;
        int j = i >> 5, dd = (i & 31) * 4;
        float4 wv = *(const float4*)&Wfc[j * D_MODEL + dd];
        uint32_t h0, l0, h1, l1;
        split_pair_h(wv.x, wv.y, h0, l0);
        split_pair_h(wv.z, wv.w, h1, l1);
        Whi[j * WSTR + (dd >> 1)]     = h0;
        Whi[j * WSTR + (dd >> 1) + 1] = h1;
        Wlo[j * WSTR + (dd >> 1)]     = l0;
        Wlo[j * WSTR + (dd >> 1) + 1] = l1;
    }
    __syncthreads();

    const uint32_t aOff = (uint32_t)(((((mat >> 1) * 8 + rin) + mt * 16) * ASTR + (mat & 1) * 4) * 4);
    const uint32_t aAddrHi = smem_u32(Ahi) + aOff;
    const uint32_t aAddrLo = smem_u32(Alo) + aOff;
    const uint32_t wOff = (uint32_t)(((((mat >> 1) * 8 + rin) + jh * 64) * WSTR + (mat & 1) * 4) * 4);
    const uint32_t wAddrHi = smem_u32(Whi) + wOff;
    const uint32_t wAddrLo = smem_u32(Wlo) + wOff;

    float c[8][4];
#pragma unroll
    for (int jt = 0; jt < 8; ++jt)
#pragma unroll
        for (int i = 0; i < 4; ++i) c[jt][i] = 0.f;

#pragma unroll
    for (int ks = 0; ks < 8; ++ks) {
        uint32_t mh[4], ml[4];
        ldmx4(mh, aAddrHi + (uint32_t)(ks * 32));
        ldmx4(ml, aAddrLo + (uint32_t)(ks * 32));
        uint32_t ah[4] = {mh[0], mh[2], mh[1], mh[3]};
        uint32_t al[4] = {ml[0], ml[2], ml[1], ml[3]};
#pragma unroll
        for (int jp = 0; jp < 4; ++jp) {
            uint32_t bh4[4], bl4[4];
            const uint32_t off = (uint32_t)((jp * 16 * WSTR + ks * 8) * 4);
            ldmx4(bh4, wAddrHi + off);
            ldmx4(bl4, wAddrLo + off);
#pragma unroll
            for (int q2 = 0; q2 < 2; ++q2) {
                float* cj = c[jp * 2 + q2];
                mma16816(cj, ah, bh4 + 2 * q2);
                mma16816(cj, ah, bl4 + 2 * q2);
                mma16816(cj, al, bh4 + 2 * q2);
            }
        }
    }

    const int nglob = n0 + mt * 16 + g;
#pragma unroll
    for (int jt = 0; jt < 8; ++jt) {
        const int j = jh * 64 + jt * 8 + 2 * m4;
        const float2 bj = *(const float2*)&bfc[j];
        float* o0 = &out[((size_t)b * D_MODEL + j) * N_SEQ];
        float* o1 = &out[((size_t)b * D_MODEL + j + 1) * N_SEQ];
        o0[nglob]     = c[jt][0] + bj.x;
        o1[nglob]     = c[jt][1] + bj.y;
        o0[nglob + 8] = c[jt][2] + bj.x;
        o1[nglob + 8] = c[jt][3] + bj.y;
    }
}

// ===========================================================================
extern "C" void kernel_launch(void* const* d_in, const int* in_sizes, int n_in,
                              void* d_out, int out_size)
{
    const float* x    = (const float*)d_in[0];
    const float* mask = (const float*)d_in[1];
    const float* Wq   = (const float*)d_in[2];
    const float* bq   = (const float*)d_in[3];
    const float* Wk   = (const float*)d_in[4];
    const float* bk   = (const float*)d_in[5];
    const float* Wv   = (const float*)d_in[6];
    const float* bv   = (const float*)d_in[7];
    const float* Wfc  = (const float*)d_in[8];
    const float* bfc  = (const float*)d_in[9];
    float* out = (float*)d_out;

    cudaFuncSetAttribute(qkv_proj_kernel, cudaFuncAttributeMaxDynamicSharedMemorySize, QKV_SMEM);
    cudaFuncSetAttribute(fc_proj_kernel,  cudaFuncAttributeMaxDynamicSharedMemorySize, FC_SMEM);

    qkv_proj_kernel<<<dim3(N_SEQ / 128, BATCH, 3), 512, QKV_SMEM>>>(x, Wq, bq, Wk, bk, Wv, bv);
    flash_attn_mma_kernel<<<dim3(N_SEQ / 256, N_HEAD, BATCH), 256>>>(mask);
    fc_proj_kernel<<<dim3(N_SEQ / 64, BATCH), 256, FC_SMEM>>>(Wfc, bfc, out);
}